// round 5
// baseline (speedup 1.0000x reference)
#include <cuda_runtime.h>

// Problem constants
#define BB    8
#define TT    2048
#define CIN   7
#define CC    8
#define NCH   128      // chunks per batch
#define CHK   16       // steps per chunk
#define NSEG  8        // segments per batch (NCH / CHK)
#define SIZE  4680     // 8 + 64 + 512 + 4096
#define STRIDE 4736    // padded row stride (floats)
#define O2    8
#define O3    72
#define O4    584
#define HDIM  256
#define NSL   16       // gemv slices
#define GEMV_BLOCKS (BB * NSL)   // 128

// Scratch (device globals -- no runtime allocation)
__device__ float g_bufA[(size_t)BB * NCH * STRIDE];   // chunk sigs
__device__ float g_bufB[(size_t)BB * NCH * STRIDE];   // local prefixes
__device__ float g_T[(size_t)BB * NSEG * STRIDE];     // scanned totals P[1..7]
__device__ float g_pool[BB * SIZE];                   // SUM over chunks (mean later)
__device__ float g_hp[NSL * BB * HDIM];
__device__ unsigned int g_cnt;

// ---------------------------------------------------------------------------
// Kernel 1: per-chunk signature via Chen iteration of exp(d_s) factors.
// ---------------------------------------------------------------------------
__global__ void __launch_bounds__(256) k_chunksig(const float* __restrict__ x)
{
    int blk = blockIdx.x;          // b*NCH + n
    int b = blk >> 7, n = blk & 127;
    int tid = threadIdx.x;

    __shared__ float d[CHK][CC];
    __shared__ __align__(16) float c[O4];

    if (tid < CHK * CC) {
        int s = tid >> 3, ch = tid & 7;
        int t = n * CHK + s;
        float v;
        if (ch < CIN) {
            float cur  = x[(b * TT + t) * CIN + ch];
            float prev = (t > 0) ? x[(b * TT + t - 1) * CIN + ch] : 0.0f;
            v = cur - prev;
        } else {
            v = (t > 0) ? (1.0f / 2047.0f) : 0.0f;
        }
        d[s][ch] = v;
    }
    __syncthreads();

    const int l = tid & 7, k = (tid >> 3) & 7, j0 = tid >> 6;
    float r4[16];

    {
        float d8[8];
        #pragma unroll
        for (int i = 0; i < 8; i++) d8[i] = d[0][i];
        float dl = d8[l], dk = d8[k], dkl = dk * dl;
        float dje = d8[j0], djo = d8[j0 + 4];
        #pragma unroll
        for (int m = 0; m < 16; m++) {
            float dj = (m & 1) ? djo : dje;
            r4[m] = d8[m >> 1] * dj * dkl * (1.0f / 24.0f);
        }
        c[O3 + tid]       = dje * dkl * (1.0f / 6.0f);
        c[O3 + tid + 256] = djo * dkl * (1.0f / 6.0f);
        if (tid < 64) c[O2 + tid] = d8[tid >> 3] * d8[tid & 7] * 0.5f;
        if (tid < 8)  c[tid] = d8[tid];
    }

    for (int s = 1; s < CHK; s++) {
        __syncthreads();
        float d8[8], c1r[8];
        #pragma unroll
        for (int i = 0; i < 8; i++) d8[i] = d[s][i];
        #pragma unroll
        for (int i = 0; i < 8; i++) c1r[i] = c[i];
        float dl = d8[l], dk = d8[k], dkl = dk * dl;
        float dje = d8[j0], djo = d8[j0 + 4];
        float djkle = dje * dkl, djklo = djo * dkl;
        float hdkl = 0.5f * dkl;
        #pragma unroll
        for (int m = 0; m < 16; m++) {
            float c3 = c[O3 + (tid >> 3) + 32 * m];
            float c2 = c[O2 + (tid >> 6) + 4 * m];
            float djkl = (m & 1) ? djklo : djkle;
            r4[m] += c3 * dl + c2 * hdkl
                   + c1r[m >> 1] * ((1.0f / 6.0f) * djkl)
                   + d8[m >> 1] * djkl * (1.0f / 24.0f);
        }
        float cO3a = c[O3 + tid], cO3b = c[O3 + tid + 256];
        float c2qa = c[O2 + (tid >> 3)], c2qb = c[O2 + (tid >> 3) + 32];
        float t3a = cO3a + c2qa * dl + c1r[j0]     * hdkl + djkle * (1.0f / 6.0f);
        float t3b = cO3b + c2qb * dl + c1r[j0 + 4] * hdkl + djklo * (1.0f / 6.0f);
        float t2 = 0.0f, t1 = 0.0f;
        if (tid < 64) t2 = c[O2 + tid] + c1r[tid >> 3] * d8[tid & 7]
                         + d8[tid >> 3] * d8[tid & 7] * 0.5f;
        if (tid < 8)  t1 = c1r[tid] + d8[tid];
        __syncthreads();
        c[O3 + tid] = t3a; c[O3 + tid + 256] = t3b;
        if (tid < 64) c[O2 + tid] = t2;
        if (tid < 8)  c[tid] = t1;
    }
    __syncthreads();

    float* o = g_bufA + (size_t)blk * STRIDE;
    for (int t = tid; t < O4; t += 256) o[t] = c[t];
    #pragma unroll
    for (int m = 0; m < 16; m++) o[O4 + tid + 256 * m] = r4[m];
}

// ---------------------------------------------------------------------------
// Kernel 2: serial local prefix product within each 16-chunk segment.
// ---------------------------------------------------------------------------
__global__ void __launch_bounds__(512) k_segscan()
{
    int blk = blockIdx.x;
    int tid = threadIdx.x;
    __shared__ __align__(16) float c[O4];
    __shared__ __align__(16) float bl[2][O4];

    size_t base = (size_t)blk * CHK * STRIDE;
    const float* A0 = g_bufA + base;
    float* Out = g_bufB + base;

    float4 r4v[2];
    for (int t = tid; t < O4; t += 512) { float v = A0[t]; c[t] = v; Out[t] = v; }
    #pragma unroll
    for (int m2 = 0; m2 < 2; m2++) {
        int p = 4 * tid + 2048 * m2;
        float4 v = *(const float4*)&A0[O4 + p];
        r4v[m2] = v;
        *(float4*)&Out[O4 + p] = v;
    }
    {
        const float* A1 = A0 + STRIDE;
        for (int t = tid; t < O4; t += 512) bl[0][t] = A1[t];
    }

    for (int ci = 1; ci < CHK; ci++) {
        int cur = (ci - 1) & 1, nxt = ci & 1;
        __syncthreads();
        if (ci + 1 < CHK) {
            const float* An = A0 + (size_t)(ci + 1) * STRIDE;
            for (int t = tid; t < O4; t += 512) bl[nxt][t] = An[t];
        }
        const float* Bg = A0 + (size_t)ci * STRIDE;
        const float* bb = bl[cur];

        float4 b1v = *(const float4*)&bb[(4 * tid) & 7];
        float4 b2v = *(const float4*)&bb[O2 + ((4 * tid) & 63)];
        float4 b3v = *(const float4*)&bb[O3 + 4 * (tid & 127)];
        float c1r[8];
        #pragma unroll
        for (int i = 0; i < 8; i++) c1r[i] = c[i];

        #pragma unroll
        for (int m2 = 0; m2 < 2; m2++) {
            int p = 4 * tid + 2048 * m2;
            float a1 = c1r[(tid >> 7) + 4 * m2];
            float a2 = c[O2 + (tid >> 4) + 32 * m2];
            float a3 = c[O3 + (tid >> 1) + 256 * m2];
            float4 Bv = *(const float4*)&Bg[O4 + p];
            r4v[m2].x += Bv.x + a1 * b3v.x + a2 * b2v.x + a3 * b1v.x;
            r4v[m2].y += Bv.y + a1 * b3v.y + a2 * b2v.y + a3 * b1v.y;
            r4v[m2].z += Bv.z + a1 * b3v.z + a2 * b2v.z + a3 * b1v.z;
            r4v[m2].w += Bv.w + a1 * b3v.w + a2 * b2v.w + a3 * b1v.w;
        }
        float b3s = bb[O3 + tid], b2s = bb[O2 + (tid & 63)], b1s = bb[tid & 7];
        float t3 = c[O3 + tid] + b3s + c1r[tid >> 6] * b2s + c[O2 + (tid >> 3)] * b1s;
        float t2 = 0.0f, t1 = 0.0f;
        if (tid < 64) t2 = c[O2 + tid] + bb[O2 + tid] + c1r[tid >> 3] * bb[tid & 7];
        if (tid < 8)  t1 = c1r[tid] + bb[tid];
        __syncthreads();
        c[O3 + tid] = t3;
        if (tid < 64) c[O2 + tid] = t2;
        if (tid < 8)  c[tid] = t1;
        float* Op = Out + (size_t)ci * STRIDE;
        Op[O3 + tid] = t3;
        if (tid < 64) Op[O2 + tid] = t2;
        if (tid < 8)  Op[tid] = t1;
        #pragma unroll
        for (int m2 = 0; m2 < 2; m2++)
            *(float4*)&Op[O4 + 4 * tid + 2048 * m2] = r4v[m2];
    }
}

// ---------------------------------------------------------------------------
// Kernel 3: Sklansky scan of 8 segment totals; also zeros g_pool and g_cnt.
// ---------------------------------------------------------------------------
__global__ void __launch_bounds__(512) k_offsets_sk()
{
    int b = blockIdx.x;
    int tid = threadIdx.x;
    int g = tid >> 7, gt = tid & 127;

    __shared__ __align__(16) float low[8][O4];

    // side duty: zero pooled accumulator + arrival counter
    for (int t = tid; t < SIZE; t += 512) g_pool[b * SIZE + t] = 0.0f;
    if (b == 0 && tid == 0) g_cnt = 0u;

    for (int s = 0; s < 8; s++) {
        const float* T = g_bufB + (size_t)(b * NCH + s * CHK + CHK - 1) * STRIDE;
        for (int t = tid; t < O4; t += 512) low[s][t] = T[t];
    }
    __syncthreads();

    const int srcT[3][4] = {{0,2,4,6},{1,1,5,5},{3,3,3,3}};
    const int dstT[3][4] = {{1,3,5,7},{2,3,6,7},{4,5,6,7}};
    const int bGT [3][4] = {{0,0,0,0},{0,1,0,1},{0,1,1,1}};

    for (int r = 0; r < 3; r++) {
        int src = srcT[r][g], dst = dstT[r][g];
        const float* A4 = (r == 0)
            ? g_bufB + (size_t)(b * NCH + src * CHK + CHK - 1) * STRIDE
            : g_T + (size_t)(b * NSEG + src) * STRIDE;
        const float* B4 = bGT[r][g]
            ? g_T + (size_t)(b * NSEG + dst) * STRIDE
            : g_bufB + (size_t)(b * NCH + dst * CHK + CHK - 1) * STRIDE;
        float* Od = g_T + (size_t)(b * NSEG + dst) * STRIDE;

        const float* as = low[src];
        float* bs = low[dst];

        float4 b1v = *(const float4*)&bs[(4 * gt) & 7];
        float4 b2v = *(const float4*)&bs[O2 + ((4 * gt) & 63)];
        float4 b3v = *(const float4*)&bs[O3 + 4 * gt];

        float4 r4o[8];
        #pragma unroll
        for (int m = 0; m < 8; m++) {
            int p = 4 * gt + 512 * m;
            float a1 = as[m];
            float a2 = as[O2 + (gt >> 4) + 8 * m];
            float a3 = as[O3 + (gt >> 1) + 64 * m];
            float4 Av = *(const float4*)&A4[O4 + p];
            float4 Bv = *(const float4*)&B4[O4 + p];
            float4 o;
            o.x = Av.x + Bv.x + a1 * b3v.x + a2 * b2v.x + a3 * b1v.x;
            o.y = Av.y + Bv.y + a1 * b3v.y + a2 * b2v.y + a3 * b1v.y;
            o.z = Av.z + Bv.z + a1 * b3v.z + a2 * b2v.z + a3 * b1v.z;
            o.w = Av.w + Bv.w + a1 * b3v.w + a2 * b2v.w + a3 * b1v.w;
            r4o[m] = o;
        }
        float4 a3v = *(const float4*)&as[O3 + 4 * gt];
        float a1q = as[gt >> 4];
        float a2q = as[O2 + (gt >> 1)];
        float4 t3;
        t3.x = a3v.x + b3v.x + a1q * b2v.x + a2q * b1v.x;
        t3.y = a3v.y + b3v.y + a1q * b2v.y + a2q * b1v.y;
        t3.z = a3v.z + b3v.z + a1q * b2v.z + a2q * b1v.z;
        t3.w = a3v.w + b3v.w + a1q * b2v.w + a2q * b1v.w;
        float t2 = 0.0f, t1 = 0.0f;
        if (gt < 64) t2 = as[O2 + gt] + bs[O2 + gt] + as[gt >> 3] * bs[gt & 7];
        if (gt < 8)  t1 = as[gt] + bs[gt];
        __syncthreads();
        #pragma unroll
        for (int m = 0; m < 8; m++)
            *(float4*)&Od[O4 + 4 * gt + 512 * m] = r4o[m];
        *(float4*)&bs[O3 + 4 * gt] = t3;
        if (gt < 64) bs[O2 + gt] = t2;
        if (gt < 8)  bs[gt] = t1;
        __syncthreads();
    }

    for (int s = 1; s < 8; s++) {
        float* Od = g_T + (size_t)(b * NSEG + s) * STRIDE;
        for (int t = tid; t < O4; t += 512) Od[t] = low[s][t];
    }
}

// ---------------------------------------------------------------------------
// Kernel 4: fused apply (offset (x) local) + truncated log + POOL accumulate.
// 512 blocks x 256 threads; each block handles 2 consecutive chunks (same
// segment), accumulates log values in registers, atomically adds to g_pool.
// ---------------------------------------------------------------------------
__global__ void __launch_bounds__(256) k_apply_pool()
{
    int blk = blockIdx.x;                 // b*64 + gi,  gi = chunk-pair index
    int b = blk >> 6, gi = blk & 63;
    int n0 = gi * 2;
    int seg = gi >> 3;                    // n0>>4
    int tid = threadIdx.x;

    __shared__ __align__(16) float s[O4];
    __shared__ __align__(16) float al[O4];
    __shared__ __align__(16) float blw[O4];
    __shared__ __align__(16) float P2_2[64];
    __shared__ __align__(16) float P2_3[512];
    __shared__ __align__(16) float P3_3[512];

    // pool accumulators (registers)
    float4 pr[4];
    #pragma unroll
    for (int m4 = 0; m4 < 4; m4++) pr[m4] = make_float4(0.f, 0.f, 0.f, 0.f);
    float pl3a = 0.f, pl3b = 0.f, pl2 = 0.f, pl1 = 0.f;

    const float* A = 0;
    if (seg > 0) {
        A = (seg == 1)
            ? g_bufB + (size_t)(b * NCH + CHK - 1) * STRIDE
            : g_T + (size_t)(b * NSEG + seg - 1) * STRIDE;
        for (int t = tid; t < O4; t += 256) al[t] = A[t];
    }

    for (int cc = 0; cc < 2; cc++) {
        int n = n0 + cc;
        const float* L = g_bufB + (size_t)(b * NCH + n) * STRIDE;
        float4 r4v[4];

        __syncthreads();   // protect blw/s/P arrays from previous chunk's readers
        if (seg == 0) {
            for (int t = tid; t < O4; t += 256) s[t] = L[t];
            #pragma unroll
            for (int m4 = 0; m4 < 4; m4++)
                r4v[m4] = *(const float4*)&L[O4 + 4 * tid + 1024 * m4];
            __syncthreads();
        } else {
            for (int t = tid; t < O4; t += 256) blw[t] = L[t];
            __syncthreads();
            for (int t = tid; t < O4; t += 256) {
                float r;
                if (t >= O3) {
                    int q = t - O3;
                    r = al[t] + blw[t]
                      + al[q >> 6]        * blw[O2 + (q & 63)]
                      + al[O2 + (q >> 3)] * blw[q & 7];
                } else if (t >= O2) {
                    int u = t - O2;
                    r = al[t] + blw[t] + al[u >> 3] * blw[u & 7];
                } else {
                    r = al[t] + blw[t];
                }
                s[t] = r;
            }
            float a1r[8];
            #pragma unroll
            for (int i = 0; i < 8; i++) a1r[i] = al[i];
            float4 b1v = *(const float4*)&blw[(4 * tid) & 7];
            float4 b2v = *(const float4*)&blw[O2 + ((4 * tid) & 63)];
            float4 b3v = *(const float4*)&blw[O3 + 4 * (tid & 127)];
            #pragma unroll
            for (int m4 = 0; m4 < 4; m4++) {
                int p = 4 * tid + 1024 * m4;
                float a1 = a1r[(tid >> 7) + 2 * m4];
                float a2 = al[O2 + (tid >> 4) + 16 * m4];
                float a3 = al[O3 + (tid >> 1) + 128 * m4];
                float4 Av = *(const float4*)&A[O4 + p];
                float4 Lv = *(const float4*)&L[O4 + p];
                float4 o;
                o.x = Av.x + Lv.x + a1 * b3v.x + a2 * b2v.x + a3 * b1v.x;
                o.y = Av.y + Lv.y + a1 * b3v.y + a2 * b2v.y + a3 * b1v.y;
                o.z = Av.z + Lv.z + a1 * b3v.z + a2 * b2v.z + a3 * b1v.z;
                o.w = Av.w + Lv.w + a1 * b3v.w + a2 * b2v.w + a3 * b1v.w;
                r4v[m4] = o;
            }
            __syncthreads();
        }

        // ---- truncated log, folded into r4v ----
        float s1r[8];
        #pragma unroll
        for (int i = 0; i < 8; i++) s1r[i] = s[i];
        float4 s1v = *(const float4*)&s[(4 * tid) & 7];
        float4 s2v = *(const float4*)&s[O2 + ((4 * tid) & 63)];
        float4 s3v = *(const float4*)&s[O3 + 4 * (tid & 127)];
        float s2f = s[O2 + (tid & 63)], s1f = s[tid & 7];
        float s3a = s[O3 + tid], s3b = s[O3 + tid + 256];

        #pragma unroll
        for (int m4 = 0; m4 < 4; m4++) {
            float a1 = s1r[(tid >> 7) + 2 * m4];
            float a2 = s[O2 + (tid >> 4) + 16 * m4];
            float a3 = s[O3 + (tid >> 1) + 128 * m4];
            r4v[m4].x -= 0.5f * (a1 * s3v.x + a2 * s2v.x + a3 * s1v.x);
            r4v[m4].y -= 0.5f * (a1 * s3v.y + a2 * s2v.y + a3 * s1v.y);
            r4v[m4].z -= 0.5f * (a1 * s3v.z + a2 * s2v.z + a3 * s1v.z);
            r4v[m4].w -= 0.5f * (a1 * s3v.w + a2 * s2v.w + a3 * s1v.w);
        }
        {
            float pa = s1r[tid >> 6] * s2f + s[O2 + (tid >> 3)] * s1f;
            float pb = s1r[(tid >> 6) + 4] * s2f + s[O2 + (tid >> 3) + 32] * s1f;
            P2_3[tid] = pa; P2_3[tid + 256] = pb;
        }
        if (tid < 64) P2_2[tid] = s1r[tid >> 3] * s[tid & 7];
        __syncthreads();

        {
            float4 P23v = *(const float4*)&P2_3[4 * (tid & 127)];
            float4 P22v = *(const float4*)&P2_2[(4 * tid) & 63];
            #pragma unroll
            for (int m4 = 0; m4 < 4; m4++) {
                float a1 = s1r[(tid >> 7) + 2 * m4];
                float a2 = s[O2 + (tid >> 4) + 16 * m4];
                r4v[m4].x += (1.0f / 3.0f) * (a1 * P23v.x + a2 * P22v.x);
                r4v[m4].y += (1.0f / 3.0f) * (a1 * P23v.y + a2 * P22v.y);
                r4v[m4].z += (1.0f / 3.0f) * (a1 * P23v.z + a2 * P22v.z);
                r4v[m4].w += (1.0f / 3.0f) * (a1 * P23v.w + a2 * P22v.w);
            }
            float P22a = P2_2[tid & 63];
            P3_3[tid]       = s1r[tid >> 6] * P22a;
            P3_3[tid + 256] = s1r[(tid >> 6) + 4] * P22a;
        }
        __syncthreads();

        {
            float4 P33v = *(const float4*)&P3_3[4 * (tid & 127)];
            #pragma unroll
            for (int m4 = 0; m4 < 4; m4++) {
                float a1 = s1r[(tid >> 7) + 2 * m4];
                r4v[m4].x -= 0.25f * a1 * P33v.x;
                r4v[m4].y -= 0.25f * a1 * P33v.y;
                r4v[m4].z -= 0.25f * a1 * P33v.z;
                r4v[m4].w -= 0.25f * a1 * P33v.w;
                pr[m4].x += r4v[m4].x;
                pr[m4].y += r4v[m4].y;
                pr[m4].z += r4v[m4].z;
                pr[m4].w += r4v[m4].w;
            }
            pl3a += s3a - 0.5f * P2_3[tid]       + (1.0f / 3.0f) * P3_3[tid];
            pl3b += s3b - 0.5f * P2_3[tid + 256] + (1.0f / 3.0f) * P3_3[tid + 256];
        }
        if (tid < 64) pl2 += s[O2 + tid] - 0.5f * P2_2[tid];
        if (tid < 8)  pl1 += s1r[tid];
    }

    // ---- atomic pool accumulation ----
    float* P = g_pool + b * SIZE;
    #pragma unroll
    for (int m4 = 0; m4 < 4; m4++) {
        int p = 4 * tid + 1024 * m4;
        atomicAdd(&P[O4 + p + 0], pr[m4].x);
        atomicAdd(&P[O4 + p + 1], pr[m4].y);
        atomicAdd(&P[O4 + p + 2], pr[m4].z);
        atomicAdd(&P[O4 + p + 3], pr[m4].w);
    }
    atomicAdd(&P[O3 + tid], pl3a);
    atomicAdd(&P[O3 + tid + 256], pl3b);
    if (tid < 64) atomicAdd(&P[O2 + tid], pl2);
    if (tid < 8)  atomicAdd(&P[tid], pl1);
}

// ---------------------------------------------------------------------------
// Kernel 5: fused MLP. 128 blocks compute GEMV partials; the last block to
// finish reduces partials + relu + W2 dot + writes out.
// ---------------------------------------------------------------------------
__global__ void __launch_bounds__(256) k_mlp(const float* __restrict__ W1,
                                             const float* __restrict__ b1,
                                             const float* __restrict__ W2,
                                             const float* __restrict__ b2,
                                             float* __restrict__ out)
{
    int blk = blockIdx.x;              // b*NSL + sl
    int b = blk / NSL, sl = blk % NSL;
    int j = threadIdx.x;

    __shared__ float sm_pv[293];
    __shared__ float red[256];
    __shared__ bool last;

    int i0 = sl * 293;
    int len = SIZE - i0; if (len > 293) len = 293;
    for (int t = j; t < len; t += 256)
        sm_pv[t] = g_pool[b * SIZE + i0 + t] * (1.0f / NCH);
    __syncthreads();

    float acc = 0.0f;
    for (int ii = 0; ii < len; ii++)
        acc = fmaf(sm_pv[ii], __ldg(&W1[(size_t)(i0 + ii) * HDIM + j]), acc);
    g_hp[(sl * BB + b) * HDIM + j] = acc;

    __threadfence();
    __syncthreads();
    if (j == 0) {
        unsigned int old = atomicAdd(&g_cnt, 1u);
        last = (old == GEMV_BLOCKS - 1);
    }
    __syncthreads();
    if (!last) return;

    __threadfence();   // acquire: make all partials visible
    for (int bb = 0; bb < BB; bb++) {
        float h = 0.0f;
        #pragma unroll
        for (int sl2 = 0; sl2 < NSL; sl2++)
            h += g_hp[(sl2 * BB + bb) * HDIM + j];
        float v = fmaxf(h + b1[j], 0.0f) * W2[j];
        red[j] = v; __syncthreads();
        for (int s2 = 128; s2 > 0; s2 >>= 1) {
            if (j < s2) red[j] += red[j + s2];
            __syncthreads();
        }
        if (j == 0) out[bb] = red[0] + b2[0];
        __syncthreads();
    }
}

// ---------------------------------------------------------------------------
extern "C" void kernel_launch(void* const* d_in, const int* in_sizes, int n_in,
                              void* d_out, int out_size)
{
    const float* x  = (const float*)d_in[0];
    const float* W1 = (const float*)d_in[1];
    const float* b1 = (const float*)d_in[2];
    const float* W2 = (const float*)d_in[3];
    const float* b2 = (const float*)d_in[4];
    float* out = (float*)d_out;

    (void)in_sizes; (void)n_in; (void)out_size;

    k_chunksig<<<BB * NCH, 256>>>(x);
    k_segscan<<<BB * NSEG, 512>>>();
    k_offsets_sk<<<BB, 512>>>();
    k_apply_pool<<<BB * 64, 256>>>();
    k_mlp<<<GEMV_BLOCKS, 256>>>(W1, b1, W2, b2, out);
}

// round 6
// speedup vs baseline: 1.0144x; 1.0144x over previous
#include <cuda_runtime.h>

// Problem constants
#define BB    8
#define TT    2048
#define CIN   7
#define CC    8
#define NCH   128      // chunks per batch
#define CHK   16       // steps per chunk
#define SEGC  8        // chunks per segment
#define NSEGS 16       // segments per batch
#define SIZE  4680     // 8 + 64 + 512 + 4096
#define STRIDE 4736    // padded row stride (floats)
#define O2    8
#define O3    72
#define O4    584
#define HDIM  256
#define NSL   16       // gemv slices
#define GEMV_BLOCKS (BB * NSL)   // 128

// Scratch (device globals -- no runtime allocation)
__device__ float g_bufA[(size_t)BB * NCH * STRIDE];   // chunk sigs, later logs
__device__ float g_bufB[(size_t)BB * NCH * STRIDE];   // local prefixes
__device__ float g_T[(size_t)BB * NSEGS * STRIDE];    // scanned totals P[1..15]
__device__ float g_pool[BB * SIZE];
__device__ float g_hp[NSL * BB * HDIM];
__device__ unsigned int g_cnt;

// ---------------------------------------------------------------------------
// Kernel 1: per-chunk signature via Chen iteration of exp(d_s) factors.
// ---------------------------------------------------------------------------
__global__ void __launch_bounds__(256) k_chunksig(const float* __restrict__ x)
{
    int blk = blockIdx.x;          // b*NCH + n
    int b = blk >> 7, n = blk & 127;
    int tid = threadIdx.x;

    __shared__ float d[CHK][CC];
    __shared__ __align__(16) float c[O4];

    if (tid < CHK * CC) {
        int s = tid >> 3, ch = tid & 7;
        int t = n * CHK + s;
        float v;
        if (ch < CIN) {
            float cur  = x[(b * TT + t) * CIN + ch];
            float prev = (t > 0) ? x[(b * TT + t - 1) * CIN + ch] : 0.0f;
            v = cur - prev;
        } else {
            v = (t > 0) ? (1.0f / 2047.0f) : 0.0f;
        }
        d[s][ch] = v;
    }
    __syncthreads();

    const int l = tid & 7, k = (tid >> 3) & 7, j0 = tid >> 6;
    float r4[16];

    {
        float d8[8];
        #pragma unroll
        for (int i = 0; i < 8; i++) d8[i] = d[0][i];
        float dl = d8[l], dk = d8[k], dkl = dk * dl;
        float dje = d8[j0], djo = d8[j0 + 4];
        #pragma unroll
        for (int m = 0; m < 16; m++) {
            float dj = (m & 1) ? djo : dje;
            r4[m] = d8[m >> 1] * dj * dkl * (1.0f / 24.0f);
        }
        c[O3 + tid]       = dje * dkl * (1.0f / 6.0f);
        c[O3 + tid + 256] = djo * dkl * (1.0f / 6.0f);
        if (tid < 64) c[O2 + tid] = d8[tid >> 3] * d8[tid & 7] * 0.5f;
        if (tid < 8)  c[tid] = d8[tid];
    }

    for (int s = 1; s < CHK; s++) {
        __syncthreads();
        float d8[8], c1r[8];
        #pragma unroll
        for (int i = 0; i < 8; i++) d8[i] = d[s][i];
        #pragma unroll
        for (int i = 0; i < 8; i++) c1r[i] = c[i];
        float dl = d8[l], dk = d8[k], dkl = dk * dl;
        float dje = d8[j0], djo = d8[j0 + 4];
        float djkle = dje * dkl, djklo = djo * dkl;
        float hdkl = 0.5f * dkl;
        #pragma unroll
        for (int m = 0; m < 16; m++) {
            float c3 = c[O3 + (tid >> 3) + 32 * m];
            float c2 = c[O2 + (tid >> 6) + 4 * m];
            float djkl = (m & 1) ? djklo : djkle;
            r4[m] += c3 * dl + c2 * hdkl
                   + c1r[m >> 1] * ((1.0f / 6.0f) * djkl)
                   + d8[m >> 1] * djkl * (1.0f / 24.0f);
        }
        float cO3a = c[O3 + tid], cO3b = c[O3 + tid + 256];
        float c2qa = c[O2 + (tid >> 3)], c2qb = c[O2 + (tid >> 3) + 32];
        float t3a = cO3a + c2qa * dl + c1r[j0]     * hdkl + djkle * (1.0f / 6.0f);
        float t3b = cO3b + c2qb * dl + c1r[j0 + 4] * hdkl + djklo * (1.0f / 6.0f);
        float t2 = 0.0f, t1 = 0.0f;
        if (tid < 64) t2 = c[O2 + tid] + c1r[tid >> 3] * d8[tid & 7]
                         + d8[tid >> 3] * d8[tid & 7] * 0.5f;
        if (tid < 8)  t1 = c1r[tid] + d8[tid];
        __syncthreads();
        c[O3 + tid] = t3a; c[O3 + tid + 256] = t3b;
        if (tid < 64) c[O2 + tid] = t2;
        if (tid < 8)  c[tid] = t1;
    }
    __syncthreads();

    float* o = g_bufA + (size_t)blk * STRIDE;
    for (int t = tid; t < O4; t += 256) o[t] = c[t];
    #pragma unroll
    for (int m = 0; m < 16; m++) o[O4 + tid + 256 * m] = r4[m];
}

// ---------------------------------------------------------------------------
// Kernel 2: serial local prefix product within each 8-chunk segment.
// 128 blocks x 512 threads; 7 products each.
// ---------------------------------------------------------------------------
__global__ void __launch_bounds__(512) k_segscan()
{
    int blk = blockIdx.x;                 // b*NSEGS + seg
    int tid = threadIdx.x;
    __shared__ __align__(16) float c[O4];
    __shared__ __align__(16) float bl[2][O4];

    size_t base = (size_t)blk * SEGC * STRIDE;
    const float* A0 = g_bufA + base;
    float* Out = g_bufB + base;

    float4 r4v[2];
    for (int t = tid; t < O4; t += 512) { float v = A0[t]; c[t] = v; Out[t] = v; }
    #pragma unroll
    for (int m2 = 0; m2 < 2; m2++) {
        int p = 4 * tid + 2048 * m2;
        float4 v = *(const float4*)&A0[O4 + p];
        r4v[m2] = v;
        *(float4*)&Out[O4 + p] = v;
    }
    {
        const float* A1 = A0 + STRIDE;
        for (int t = tid; t < O4; t += 512) bl[0][t] = A1[t];
    }

    for (int ci = 1; ci < SEGC; ci++) {
        int cur = (ci - 1) & 1, nxt = ci & 1;
        __syncthreads();
        if (ci + 1 < SEGC) {
            const float* An = A0 + (size_t)(ci + 1) * STRIDE;
            for (int t = tid; t < O4; t += 512) bl[nxt][t] = An[t];
        }
        const float* Bg = A0 + (size_t)ci * STRIDE;
        const float* bb = bl[cur];

        float4 b1v = *(const float4*)&bb[(4 * tid) & 7];
        float4 b2v = *(const float4*)&bb[O2 + ((4 * tid) & 63)];
        float4 b3v = *(const float4*)&bb[O3 + 4 * (tid & 127)];
        float c1r[8];
        #pragma unroll
        for (int i = 0; i < 8; i++) c1r[i] = c[i];

        #pragma unroll
        for (int m2 = 0; m2 < 2; m2++) {
            int p = 4 * tid + 2048 * m2;
            float a1 = c1r[(tid >> 7) + 4 * m2];
            float a2 = c[O2 + (tid >> 4) + 32 * m2];
            float a3 = c[O3 + (tid >> 1) + 256 * m2];
            float4 Bv = *(const float4*)&Bg[O4 + p];
            r4v[m2].x += Bv.x + a1 * b3v.x + a2 * b2v.x + a3 * b1v.x;
            r4v[m2].y += Bv.y + a1 * b3v.y + a2 * b2v.y + a3 * b1v.y;
            r4v[m2].z += Bv.z + a1 * b3v.z + a2 * b2v.z + a3 * b1v.z;
            r4v[m2].w += Bv.w + a1 * b3v.w + a2 * b2v.w + a3 * b1v.w;
        }
        float b3s = bb[O3 + tid], b2s = bb[O2 + (tid & 63)], b1s = bb[tid & 7];
        float t3 = c[O3 + tid] + b3s + c1r[tid >> 6] * b2s + c[O2 + (tid >> 3)] * b1s;
        float t2 = 0.0f, t1 = 0.0f;
        if (tid < 64) t2 = c[O2 + tid] + bb[O2 + tid] + c1r[tid >> 3] * bb[tid & 7];
        if (tid < 8)  t1 = c1r[tid] + bb[tid];
        __syncthreads();
        c[O3 + tid] = t3;
        if (tid < 64) c[O2 + tid] = t2;
        if (tid < 8)  c[tid] = t1;
        float* Op = Out + (size_t)ci * STRIDE;
        Op[O3 + tid] = t3;
        if (tid < 64) Op[O2 + tid] = t2;
        if (tid < 8)  Op[tid] = t1;
        #pragma unroll
        for (int m2 = 0; m2 < 2; m2++)
            *(float4*)&Op[O4 + 4 * tid + 2048 * m2] = r4v[m2];
    }
}

// ---------------------------------------------------------------------------
// Kernel 3: Sklansky scan of 16 segment totals per batch.
// 8 blocks x 1024 threads = 8 groups of 128; 8 muls/round x 4 rounds.
// Lows (16 x 584) in smem; L4 in g_T (L2-hot). Also resets g_cnt.
// ---------------------------------------------------------------------------
__global__ void __launch_bounds__(1024) k_sklansky()
{
    int b = blockIdx.x;
    int tid = threadIdx.x;
    int g = tid >> 7, gt = tid & 127;

    __shared__ __align__(16) float low[NSEGS][O4];

    if (b == 0 && tid == 0) g_cnt = 0u;

    for (int s = 0; s < NSEGS; s++) {
        const float* T = g_bufB + (size_t)(b * NCH + s * SEGC + SEGC - 1) * STRIDE;
        for (int t = tid; t < O4; t += 1024) low[s][t] = T[t];
    }
    __syncthreads();

    #pragma unroll
    for (int r = 0; r < 4; r++) {
        int src, dst; bool bnew;
        if (r == 0)      { src = 2 * g;                dst = 2 * g + 1;                    bnew = true; }
        else if (r == 1) { int e = 4 * (g >> 1); src = e + 1; dst = e + 2 + (g & 1);       bnew = (g & 1) == 0; }
        else if (r == 2) { int e = 8 * (g >> 2); src = e + 3; dst = e + 4 + (g & 3);       bnew = (g & 3) == 0; }
        else             { src = 7;                    dst = 8 + g;                        bnew = (g == 0); }

        const float* A4 = (r == 0)
            ? g_bufB + (size_t)(b * NCH + src * SEGC + SEGC - 1) * STRIDE
            : g_T + (size_t)(b * NSEGS + src) * STRIDE;
        const float* B4 = bnew
            ? g_bufB + (size_t)(b * NCH + dst * SEGC + SEGC - 1) * STRIDE
            : g_T + (size_t)(b * NSEGS + dst) * STRIDE;
        float* Od = g_T + (size_t)(b * NSEGS + dst) * STRIDE;

        const float* as = low[src];
        float* bs = low[dst];

        float4 b1v = *(const float4*)&bs[(4 * gt) & 7];
        float4 b2v = *(const float4*)&bs[O2 + ((4 * gt) & 63)];
        float4 b3v = *(const float4*)&bs[O3 + 4 * gt];

        float4 r4o[8];
        #pragma unroll
        for (int m = 0; m < 8; m++) {
            int p = 4 * gt + 512 * m;
            float a1 = as[m];
            float a2 = as[O2 + (gt >> 4) + 8 * m];
            float a3 = as[O3 + (gt >> 1) + 64 * m];
            float4 Av = *(const float4*)&A4[O4 + p];
            float4 Bv = *(const float4*)&B4[O4 + p];
            float4 o;
            o.x = Av.x + Bv.x + a1 * b3v.x + a2 * b2v.x + a3 * b1v.x;
            o.y = Av.y + Bv.y + a1 * b3v.y + a2 * b2v.y + a3 * b1v.y;
            o.z = Av.z + Bv.z + a1 * b3v.z + a2 * b2v.z + a3 * b1v.z;
            o.w = Av.w + Bv.w + a1 * b3v.w + a2 * b2v.w + a3 * b1v.w;
            r4o[m] = o;
        }
        float4 a3v = *(const float4*)&as[O3 + 4 * gt];
        float a1q = as[gt >> 4];
        float a2q = as[O2 + (gt >> 1)];
        float4 t3;
        t3.x = a3v.x + b3v.x + a1q * b2v.x + a2q * b1v.x;
        t3.y = a3v.y + b3v.y + a1q * b2v.y + a2q * b1v.y;
        t3.z = a3v.z + b3v.z + a1q * b2v.z + a2q * b1v.z;
        t3.w = a3v.w + b3v.w + a1q * b2v.w + a2q * b1v.w;
        float t2 = 0.0f, t1 = 0.0f;
        if (gt < 64) t2 = as[O2 + gt] + bs[O2 + gt] + as[gt >> 3] * bs[gt & 7];
        if (gt < 8)  t1 = as[gt] + bs[gt];
        __syncthreads();   // all reads of lows done
        #pragma unroll
        for (int m = 0; m < 8; m++)
            *(float4*)&Od[O4 + 4 * gt + 512 * m] = r4o[m];
        *(float4*)&bs[O3 + 4 * gt] = t3;
        if (gt < 64) bs[O2 + gt] = t2;
        if (gt < 8)  bs[gt] = t1;
        __syncthreads();   // writes visible (smem + global) for next round
    }

    for (int s = 1; s < NSEGS; s++) {
        float* Od = g_T + (size_t)(b * NSEGS + s) * STRIDE;
        for (int t = tid; t < O4; t += 1024) Od[t] = low[s][t];
    }
}

// ---------------------------------------------------------------------------
// Kernel 4: fused apply (offset (x) local) + truncated log -> g_bufA.
// 1024 blocks x 256 threads (round-4 form; regs ~48, occ ~62%).
// ---------------------------------------------------------------------------
__global__ void __launch_bounds__(256) k_apply_log()
{
    int blk = blockIdx.x;                 // b*NCH + n
    int b = blk >> 7, n = blk & 127;
    int seg = n >> 3;                     // segment of 8 chunks
    int tid = threadIdx.x;

    __shared__ __align__(16) float s[O4];
    __shared__ __align__(16) float al[O4];
    __shared__ __align__(16) float blw[O4];
    __shared__ __align__(16) float P2_2[64];
    __shared__ __align__(16) float P2_3[512];
    __shared__ __align__(16) float P3_3[512];

    const float* L = g_bufB + (size_t)blk * STRIDE;
    float4 r4v[4];

    if (seg == 0) {
        for (int t = tid; t < O4; t += 256) s[t] = L[t];
        #pragma unroll
        for (int m4 = 0; m4 < 4; m4++)
            r4v[m4] = *(const float4*)&L[O4 + 4 * tid + 1024 * m4];
    } else {
        const float* A = (seg == 1)
            ? g_bufB + (size_t)(b * NCH + SEGC - 1) * STRIDE
            : g_T + (size_t)(b * NSEGS + seg - 1) * STRIDE;
        for (int t = tid; t < O4; t += 256) { al[t] = A[t]; blw[t] = L[t]; }
        __syncthreads();
        for (int t = tid; t < O4; t += 256) {
            float r;
            if (t >= O3) {
                int q = t - O3;
                r = al[t] + blw[t]
                  + al[q >> 6]        * blw[O2 + (q & 63)]
                  + al[O2 + (q >> 3)] * blw[q & 7];
            } else if (t >= O2) {
                int u = t - O2;
                r = al[t] + blw[t] + al[u >> 3] * blw[u & 7];
            } else {
                r = al[t] + blw[t];
            }
            s[t] = r;
        }
        float a1r[8];
        #pragma unroll
        for (int i = 0; i < 8; i++) a1r[i] = al[i];
        float4 b1v = *(const float4*)&blw[(4 * tid) & 7];
        float4 b2v = *(const float4*)&blw[O2 + ((4 * tid) & 63)];
        float4 b3v = *(const float4*)&blw[O3 + 4 * (tid & 127)];
        #pragma unroll
        for (int m4 = 0; m4 < 4; m4++) {
            int p = 4 * tid + 1024 * m4;
            float a1 = a1r[(tid >> 7) + 2 * m4];
            float a2 = al[O2 + (tid >> 4) + 16 * m4];
            float a3 = al[O3 + (tid >> 1) + 128 * m4];
            float4 Av = *(const float4*)&A[O4 + p];
            float4 Lv = *(const float4*)&L[O4 + p];
            float4 o;
            o.x = Av.x + Lv.x + a1 * b3v.x + a2 * b2v.x + a3 * b1v.x;
            o.y = Av.y + Lv.y + a1 * b3v.y + a2 * b2v.y + a3 * b1v.y;
            o.z = Av.z + Lv.z + a1 * b3v.z + a2 * b2v.z + a3 * b1v.z;
            o.w = Av.w + Lv.w + a1 * b3v.w + a2 * b2v.w + a3 * b1v.w;
            r4v[m4] = o;
        }
    }
    __syncthreads();

    float s1r[8];
    #pragma unroll
    for (int i = 0; i < 8; i++) s1r[i] = s[i];
    float4 s1v = *(const float4*)&s[(4 * tid) & 7];
    float4 s2v = *(const float4*)&s[O2 + ((4 * tid) & 63)];
    float4 s3v = *(const float4*)&s[O3 + 4 * (tid & 127)];
    float s2f = s[O2 + (tid & 63)], s1f = s[tid & 7];
    float s3a = s[O3 + tid], s3b = s[O3 + tid + 256];

    #pragma unroll
    for (int m4 = 0; m4 < 4; m4++) {
        float a1 = s1r[(tid >> 7) + 2 * m4];
        float a2 = s[O2 + (tid >> 4) + 16 * m4];
        float a3 = s[O3 + (tid >> 1) + 128 * m4];
        r4v[m4].x -= 0.5f * (a1 * s3v.x + a2 * s2v.x + a3 * s1v.x);
        r4v[m4].y -= 0.5f * (a1 * s3v.y + a2 * s2v.y + a3 * s1v.y);
        r4v[m4].z -= 0.5f * (a1 * s3v.z + a2 * s2v.z + a3 * s1v.z);
        r4v[m4].w -= 0.5f * (a1 * s3v.w + a2 * s2v.w + a3 * s1v.w);
    }
    {
        float pa = s1r[tid >> 6] * s2f + s[O2 + (tid >> 3)] * s1f;
        float pb = s1r[(tid >> 6) + 4] * s2f + s[O2 + (tid >> 3) + 32] * s1f;
        P2_3[tid] = pa; P2_3[tid + 256] = pb;
    }
    if (tid < 64) P2_2[tid] = s1r[tid >> 3] * s[tid & 7];
    __syncthreads();

    {
        float4 P23v = *(const float4*)&P2_3[4 * (tid & 127)];
        float4 P22v = *(const float4*)&P2_2[(4 * tid) & 63];
        #pragma unroll
        for (int m4 = 0; m4 < 4; m4++) {
            float a1 = s1r[(tid >> 7) + 2 * m4];
            float a2 = s[O2 + (tid >> 4) + 16 * m4];
            r4v[m4].x += (1.0f / 3.0f) * (a1 * P23v.x + a2 * P22v.x);
            r4v[m4].y += (1.0f / 3.0f) * (a1 * P23v.y + a2 * P22v.y);
            r4v[m4].z += (1.0f / 3.0f) * (a1 * P23v.z + a2 * P22v.z);
            r4v[m4].w += (1.0f / 3.0f) * (a1 * P23v.w + a2 * P22v.w);
        }
        float P22a = P2_2[tid & 63];
        P3_3[tid]       = s1r[tid >> 6] * P22a;
        P3_3[tid + 256] = s1r[(tid >> 6) + 4] * P22a;
    }
    __syncthreads();

    float* S = g_bufA + (size_t)blk * STRIDE;
    {
        float4 P33v = *(const float4*)&P3_3[4 * (tid & 127)];
        #pragma unroll
        for (int m4 = 0; m4 < 4; m4++) {
            float a1 = s1r[(tid >> 7) + 2 * m4];
            r4v[m4].x -= 0.25f * a1 * P33v.x;
            r4v[m4].y -= 0.25f * a1 * P33v.y;
            r4v[m4].z -= 0.25f * a1 * P33v.z;
            r4v[m4].w -= 0.25f * a1 * P33v.w;
            *(float4*)&S[O4 + 4 * tid + 1024 * m4] = r4v[m4];
        }
        S[O3 + tid]       = s3a - 0.5f * P2_3[tid]       + (1.0f / 3.0f) * P3_3[tid];
        S[O3 + tid + 256] = s3b - 0.5f * P2_3[tid + 256] + (1.0f / 3.0f) * P3_3[tid + 256];
    }
    if (tid < 64) S[O2 + tid] = s[O2 + tid] - 0.5f * P2_2[tid];
    if (tid < 8)  S[tid] = s1r[tid];
}

// ---------------------------------------------------------------------------
// Kernel 5: mean over chunk dim -> pooled (B, SIZE)
// ---------------------------------------------------------------------------
__global__ void __launch_bounds__(256) k_pool()
{
    int g = blockIdx.x * 256 + threadIdx.x;
    if (g >= BB * SIZE) return;
    int b = g / SIZE, i = g - b * SIZE;
    const float* p = g_bufA + (size_t)b * NCH * STRIDE + i;
    float acc = 0.0f;
    #pragma unroll 8
    for (int n = 0; n < NCH; n++) acc += p[(size_t)n * STRIDE];
    g_pool[g] = acc * (1.0f / NCH);
}

// ---------------------------------------------------------------------------
// Kernel 6: fused MLP; last finishing block does the final reduction.
// ---------------------------------------------------------------------------
__global__ void __launch_bounds__(256) k_mlp(const float* __restrict__ W1,
                                             const float* __restrict__ b1,
                                             const float* __restrict__ W2,
                                             const float* __restrict__ b2,
                                             float* __restrict__ out)
{
    int blk = blockIdx.x;              // b*NSL + sl
    int b = blk / NSL, sl = blk % NSL;
    int j = threadIdx.x;

    __shared__ float sm_pv[293];
    __shared__ float red[256];
    __shared__ bool last;

    int i0 = sl * 293;
    int len = SIZE - i0; if (len > 293) len = 293;
    for (int t = j; t < len; t += 256)
        sm_pv[t] = g_pool[b * SIZE + i0 + t];
    __syncthreads();

    float acc = 0.0f;
    for (int ii = 0; ii < len; ii++)
        acc = fmaf(sm_pv[ii], __ldg(&W1[(size_t)(i0 + ii) * HDIM + j]), acc);
    g_hp[(sl * BB + b) * HDIM + j] = acc;

    __threadfence();
    __syncthreads();
    if (j == 0) {
        unsigned int old = atomicAdd(&g_cnt, 1u);
        last = (old == GEMV_BLOCKS - 1);
    }
    __syncthreads();
    if (!last) return;

    __threadfence();
    for (int bb = 0; bb < BB; bb++) {
        float h = 0.0f;
        #pragma unroll
        for (int sl2 = 0; sl2 < NSL; sl2++)
            h += g_hp[(sl2 * BB + bb) * HDIM + j];
        float v = fmaxf(h + b1[j], 0.0f) * W2[j];
        red[j] = v; __syncthreads();
        for (int s2 = 128; s2 > 0; s2 >>= 1) {
            if (j < s2) red[j] += red[j + s2];
            __syncthreads();
        }
        if (j == 0) out[bb] = red[0] + b2[0];
        __syncthreads();
    }
}

// ---------------------------------------------------------------------------
extern "C" void kernel_launch(void* const* d_in, const int* in_sizes, int n_in,
                              void* d_out, int out_size)
{
    const float* x  = (const float*)d_in[0];
    const float* W1 = (const float*)d_in[1];
    const float* b1 = (const float*)d_in[2];
    const float* W2 = (const float*)d_in[3];
    const float* b2 = (const float*)d_in[4];
    float* out = (float*)d_out;

    (void)in_sizes; (void)n_in; (void)out_size;

    k_chunksig<<<BB * NCH, 256>>>(x);
    k_segscan<<<BB * NSEGS, 512>>>();
    k_sklansky<<<BB, 1024>>>();
    k_apply_log<<<BB * NCH, 256>>>();
    k_pool<<<(BB * SIZE + 255) / 256, 256>>>();
    k_mlp<<<GEMV_BLOCKS, 256>>>(W1, b1, W2, b2, out);
}

// round 7
// speedup vs baseline: 1.1052x; 1.0895x over previous
#include <cuda_runtime.h>

// Problem constants
#define BB    8
#define TT    2048
#define CIN   7
#define CC    8
#define NCH   128      // chunks per batch
#define SEGC  4        // chunks per segment
#define SEGSTEPS 64    // time steps per segment
#define NSEGS 32       // segments per batch
#define NBLK  256      // persistent blocks (all co-resident at 2/SM)
#define SIZE  4680     // 8 + 64 + 512 + 4096
#define STRIDE 4736    // padded row stride (floats)
#define O2    8
#define O3    72
#define O4    584
#define HDIM  256
#define NSL   32       // gemv slices
#define SLW   147      // slice width (32*147 = 4704 >= 4680)

// Scratch (device globals -- no runtime allocation)
__device__ __align__(16) float g_bufB[(size_t)BB * NCH * STRIDE];   // local prefixes
__device__ __align__(16) float g_bufA[(size_t)BB * NCH * STRIDE];   // logs
__device__ __align__(16) float g_T[(size_t)BB * NSEGS * STRIDE];    // scanned totals
__device__ __align__(16) float g_hp[NSL * BB * HDIM];
__device__ unsigned int g_bar;   // zero-init; reset to 0 at end of every launch

// ---------------------------------------------------------------------------
// Device-wide barrier: idx-th barrier (1-based). All NBLK blocks must call.
// ---------------------------------------------------------------------------
__device__ __forceinline__ void gsync(unsigned int idx)
{
    __syncthreads();
    if (threadIdx.x == 0) {
        __threadfence();                      // release prior writes to L2
        atomicAdd(&g_bar, 1u);
        unsigned int target = idx * NBLK;
        volatile unsigned int* p = &g_bar;
        while (*p < target) { }
        __threadfence();
    }
    __syncthreads();
}

// ---------------------------------------------------------------------------
// Group merge Od = A (x) B (full levels). 256 threads. smem: al at sm, bl at
// sm+584. Global reads via __ldcg (cross-block data).
// ---------------------------------------------------------------------------
__device__ void ta_merge(const float* __restrict__ A, const float* __restrict__ Bp,
                         float* __restrict__ Od, float* sm, int tid)
{
    float* al = sm;
    float* bl = sm + 584;
    for (int t = tid; t < O4; t += 256) { al[t] = __ldcg(A + t); bl[t] = __ldcg(Bp + t); }
    __syncthreads();

    // lows
    for (int t = tid; t < O4; t += 256) {
        float r;
        if (t >= O3) {
            int q = t - O3;
            r = al[t] + bl[t] + al[q >> 6] * bl[O2 + (q & 63)]
              + al[O2 + (q >> 3)] * bl[q & 7];
        } else if (t >= O2) {
            int u = t - O2;
            r = al[t] + bl[t] + al[u >> 3] * bl[u & 7];
        } else {
            r = al[t] + bl[t];
        }
        Od[t] = r;
    }
    // level 4
    float a1r[8];
    #pragma unroll
    for (int i = 0; i < 8; i++) a1r[i] = al[i];
    float4 b1v = *(const float4*)&bl[(4 * tid) & 7];
    float4 b2v = *(const float4*)&bl[O2 + ((4 * tid) & 63)];
    float4 b3v = *(const float4*)&bl[O3 + 4 * (tid & 127)];
    #pragma unroll
    for (int m4 = 0; m4 < 4; m4++) {
        int p = 4 * tid + 1024 * m4;
        float a1 = a1r[(tid >> 7) + 2 * m4];
        float a2 = al[O2 + (tid >> 4) + 16 * m4];
        float a3 = al[O3 + (tid >> 1) + 128 * m4];
        float4 Av = __ldcg((const float4*)(A + O4 + p));
        float4 Bv = __ldcg((const float4*)(Bp + O4 + p));
        float4 o;
        o.x = Av.x + Bv.x + a1 * b3v.x + a2 * b2v.x + a3 * b1v.x;
        o.y = Av.y + Bv.y + a1 * b3v.y + a2 * b2v.y + a3 * b1v.y;
        o.z = Av.z + Bv.z + a1 * b3v.z + a2 * b2v.z + a3 * b1v.z;
        o.w = Av.w + Bv.w + a1 * b3v.w + a2 * b2v.w + a3 * b1v.w;
        *(float4*)(Od + O4 + p) = o;
    }
}

// ---------------------------------------------------------------------------
// apply+log for one chunk task. smem layout inside sm (2848 floats).
// ---------------------------------------------------------------------------
__device__ void apply_one(int task, float* sm, int tid)
{
    int b = task >> 7, n = task & 127;
    int seg = n >> 2;                 // SEGC = 4

    float* s    = sm;                 // 584
    float* al   = sm + 584;           // 584
    float* blw  = sm + 1168;          // 584
    float* P2_2 = sm + 1752;          // 64 (+pad)
    float* P2_3 = sm + 1824;          // 512
    float* P3_3 = sm + 2336;          // 512

    const float* L = g_bufB + (size_t)task * STRIDE;
    float4 r4v[4];

    if (seg == 0) {
        for (int t = tid; t < O4; t += 256) s[t] = __ldcg(L + t);
        #pragma unroll
        for (int m4 = 0; m4 < 4; m4++)
            r4v[m4] = __ldcg((const float4*)(L + O4 + 4 * tid + 1024 * m4));
    } else {
        const float* A = (seg == 1)
            ? g_bufB + (size_t)(b * NCH + SEGC - 1) * STRIDE
            : g_T + (size_t)(b * NSEGS + seg - 1) * STRIDE;
        for (int t = tid; t < O4; t += 256) { al[t] = __ldcg(A + t); blw[t] = __ldcg(L + t); }
        __syncthreads();
        for (int t = tid; t < O4; t += 256) {
            float r;
            if (t >= O3) {
                int q = t - O3;
                r = al[t] + blw[t]
                  + al[q >> 6]        * blw[O2 + (q & 63)]
                  + al[O2 + (q >> 3)] * blw[q & 7];
            } else if (t >= O2) {
                int u = t - O2;
                r = al[t] + blw[t] + al[u >> 3] * blw[u & 7];
            } else {
                r = al[t] + blw[t];
            }
            s[t] = r;
        }
        float a1r[8];
        #pragma unroll
        for (int i = 0; i < 8; i++) a1r[i] = al[i];
        float4 b1v = *(const float4*)&blw[(4 * tid) & 7];
        float4 b2v = *(const float4*)&blw[O2 + ((4 * tid) & 63)];
        float4 b3v = *(const float4*)&blw[O3 + 4 * (tid & 127)];
        #pragma unroll
        for (int m4 = 0; m4 < 4; m4++) {
            int p = 4 * tid + 1024 * m4;
            float a1 = a1r[(tid >> 7) + 2 * m4];
            float a2 = al[O2 + (tid >> 4) + 16 * m4];
            float a3 = al[O3 + (tid >> 1) + 128 * m4];
            float4 Av = __ldcg((const float4*)(A + O4 + p));
            float4 Lv = __ldcg((const float4*)(L + O4 + p));
            float4 o;
            o.x = Av.x + Lv.x + a1 * b3v.x + a2 * b2v.x + a3 * b1v.x;
            o.y = Av.y + Lv.y + a1 * b3v.y + a2 * b2v.y + a3 * b1v.y;
            o.z = Av.z + Lv.z + a1 * b3v.z + a2 * b2v.z + a3 * b1v.z;
            o.w = Av.w + Lv.w + a1 * b3v.w + a2 * b2v.w + a3 * b1v.w;
            r4v[m4] = o;
        }
    }
    __syncthreads();

    // ---- truncated log, folded into r4v ----
    float s1r[8];
    #pragma unroll
    for (int i = 0; i < 8; i++) s1r[i] = s[i];
    float4 s1v = *(const float4*)&s[(4 * tid) & 7];
    float4 s2v = *(const float4*)&s[O2 + ((4 * tid) & 63)];
    float4 s3v = *(const float4*)&s[O3 + 4 * (tid & 127)];
    float s2f = s[O2 + (tid & 63)], s1f = s[tid & 7];
    float s3a = s[O3 + tid], s3b = s[O3 + tid + 256];

    #pragma unroll
    for (int m4 = 0; m4 < 4; m4++) {
        float a1 = s1r[(tid >> 7) + 2 * m4];
        float a2 = s[O2 + (tid >> 4) + 16 * m4];
        float a3 = s[O3 + (tid >> 1) + 128 * m4];
        r4v[m4].x -= 0.5f * (a1 * s3v.x + a2 * s2v.x + a3 * s1v.x);
        r4v[m4].y -= 0.5f * (a1 * s3v.y + a2 * s2v.y + a3 * s1v.y);
        r4v[m4].z -= 0.5f * (a1 * s3v.z + a2 * s2v.z + a3 * s1v.z);
        r4v[m4].w -= 0.5f * (a1 * s3v.w + a2 * s2v.w + a3 * s1v.w);
    }
    {
        float pa = s1r[tid >> 6] * s2f + s[O2 + (tid >> 3)] * s1f;
        float pb = s1r[(tid >> 6) + 4] * s2f + s[O2 + (tid >> 3) + 32] * s1f;
        P2_3[tid] = pa; P2_3[tid + 256] = pb;
    }
    if (tid < 64) P2_2[tid] = s1r[tid >> 3] * s[tid & 7];
    __syncthreads();

    {
        float4 P23v = *(const float4*)&P2_3[4 * (tid & 127)];
        float4 P22v = *(const float4*)&P2_2[(4 * tid) & 63];
        #pragma unroll
        for (int m4 = 0; m4 < 4; m4++) {
            float a1 = s1r[(tid >> 7) + 2 * m4];
            float a2 = s[O2 + (tid >> 4) + 16 * m4];
            r4v[m4].x += (1.0f / 3.0f) * (a1 * P23v.x + a2 * P22v.x);
            r4v[m4].y += (1.0f / 3.0f) * (a1 * P23v.y + a2 * P22v.y);
            r4v[m4].z += (1.0f / 3.0f) * (a1 * P23v.z + a2 * P22v.z);
            r4v[m4].w += (1.0f / 3.0f) * (a1 * P23v.w + a2 * P22v.w);
        }
        float P22a = P2_2[tid & 63];
        P3_3[tid]       = s1r[tid >> 6] * P22a;
        P3_3[tid + 256] = s1r[(tid >> 6) + 4] * P22a;
    }
    __syncthreads();

    float* S = g_bufA + (size_t)task * STRIDE;
    {
        float4 P33v = *(const float4*)&P3_3[4 * (tid & 127)];
        #pragma unroll
        for (int m4 = 0; m4 < 4; m4++) {
            float a1 = s1r[(tid >> 7) + 2 * m4];
            r4v[m4].x -= 0.25f * a1 * P33v.x;
            r4v[m4].y -= 0.25f * a1 * P33v.y;
            r4v[m4].z -= 0.25f * a1 * P33v.z;
            r4v[m4].w -= 0.25f * a1 * P33v.w;
            *(float4*)&S[O4 + 4 * tid + 1024 * m4] = r4v[m4];
        }
        S[O3 + tid]       = s3a - 0.5f * P2_3[tid]       + (1.0f / 3.0f) * P3_3[tid];
        S[O3 + tid + 256] = s3b - 0.5f * P2_3[tid + 256] + (1.0f / 3.0f) * P3_3[tid + 256];
    }
    if (tid < 64) S[O2 + tid] = s[O2 + tid] - 0.5f * P2_2[tid];
    if (tid < 8)  S[tid] = s1r[tid];
}

// ---------------------------------------------------------------------------
// THE single fused kernel.
// ---------------------------------------------------------------------------
__global__ void __launch_bounds__(256, 2)
k_fused(const float* __restrict__ x,
        const float* __restrict__ W1,
        const float* __restrict__ b1,
        const float* __restrict__ W2,
        const float* __restrict__ b2,
        float* __restrict__ out)
{
    __shared__ __align__(16) float sm[2848];
    int blk = blockIdx.x;
    int tid = threadIdx.x;

    // warm L2 with W1 for phase 4 (spread across all threads)
    {
        size_t nbytes = (size_t)SIZE * HDIM * 4;
        size_t loff = ((size_t)blk * 256 + tid) * 128;
        if (loff < nbytes)
            asm volatile("prefetch.global.L2 [%0];" :: "l"((const char*)W1 + loff));
    }

    // ======================= Phase 1: Chen over segment =====================
    // 256 blocks = (b, seg). 64 steps; snapshots every 16 steps ARE the local
    // chunk prefixes (segscan absorbed for free).
    {
        int b = blk >> 5, seg = blk & 31;
        float* d = sm;          // [64][8]
        float* c = sm + 512;    // O4 lows

        for (int idx = tid; idx < SEGSTEPS * CC; idx += 256) {
            int s = idx >> 3, ch = idx & 7;
            int t = seg * SEGSTEPS + s;
            float v;
            if (ch < CIN) {
                float cur  = x[(b * TT + t) * CIN + ch];
                float prev = (t > 0) ? x[(b * TT + t - 1) * CIN + ch] : 0.0f;
                v = cur - prev;
            } else {
                v = (t > 0) ? (1.0f / 2047.0f) : 0.0f;
            }
            d[idx] = v;
        }
        __syncthreads();

        const int l = tid & 7, k = (tid >> 3) & 7, j0 = tid >> 6;
        float r4[16];
        {
            float d8[8];
            #pragma unroll
            for (int i = 0; i < 8; i++) d8[i] = d[i];
            float dl = d8[l], dk = d8[k], dkl = dk * dl;
            float dje = d8[j0], djo = d8[j0 + 4];
            #pragma unroll
            for (int m = 0; m < 16; m++) {
                float dj = (m & 1) ? djo : dje;
                r4[m] = d8[m >> 1] * dj * dkl * (1.0f / 24.0f);
            }
            c[O3 + tid]       = dje * dkl * (1.0f / 6.0f);
            c[O3 + tid + 256] = djo * dkl * (1.0f / 6.0f);
            if (tid < 64) c[O2 + tid] = d8[tid >> 3] * d8[tid & 7] * 0.5f;
            if (tid < 8)  c[tid] = d8[tid];
        }

        for (int s = 1; s < SEGSTEPS; s++) {
            __syncthreads();
            float d8[8], c1r[8];
            #pragma unroll
            for (int i = 0; i < 8; i++) d8[i] = d[s * 8 + i];
            #pragma unroll
            for (int i = 0; i < 8; i++) c1r[i] = c[i];
            float dl = d8[l], dk = d8[k], dkl = dk * dl;
            float dje = d8[j0], djo = d8[j0 + 4];
            float djkle = dje * dkl, djklo = djo * dkl;
            float hdkl = 0.5f * dkl;
            #pragma unroll
            for (int m = 0; m < 16; m++) {
                float c3 = c[O3 + (tid >> 3) + 32 * m];
                float c2 = c[O2 + (tid >> 6) + 4 * m];
                float djkl = (m & 1) ? djklo : djkle;
                r4[m] += c3 * dl + c2 * hdkl
                       + c1r[m >> 1] * ((1.0f / 6.0f) * djkl)
                       + d8[m >> 1] * djkl * (1.0f / 24.0f);
            }
            float cO3a = c[O3 + tid], cO3b = c[O3 + tid + 256];
            float c2qa = c[O2 + (tid >> 3)], c2qb = c[O2 + (tid >> 3) + 32];
            float t3a = cO3a + c2qa * dl + c1r[j0]     * hdkl + djkle * (1.0f / 6.0f);
            float t3b = cO3b + c2qb * dl + c1r[j0 + 4] * hdkl + djklo * (1.0f / 6.0f);
            float t2 = 0.0f, t1 = 0.0f;
            if (tid < 64) t2 = c[O2 + tid] + c1r[tid >> 3] * d8[tid & 7]
                             + d8[tid >> 3] * d8[tid & 7] * 0.5f;
            if (tid < 8)  t1 = c1r[tid] + d8[tid];
            __syncthreads();
            c[O3 + tid] = t3a; c[O3 + tid + 256] = t3b;
            if (tid < 64) c[O2 + tid] = t2;
            if (tid < 8)  c[tid] = t1;

            if ((s & 15) == 15) {   // snapshot = local prefix of chunk (s>>4)
                float* o = g_bufB + (size_t)((b * NSEGS + seg) * SEGC + (s >> 4)) * STRIDE;
                o[O3 + tid] = t3a;
                o[O3 + tid + 256] = t3b;
                if (tid < 64) o[O2 + tid] = t2;
                if (tid < 8)  o[tid] = t1;
                #pragma unroll
                for (int m = 0; m < 16; m++) o[O4 + tid + 256 * m] = r4[m];
            }
        }
    }
    gsync(1);

    // ======================= Phase 2: Sklansky over 32 ======================
    for (int r = 0; r < 5; r++) {
        if (blk < 128) {
            int b = blk >> 4, g = blk & 15;
            int span = 1 << r;
            int e_src = ((g >> r) << (r + 1)) + span - 1;
            int e_dst = ((g >> r) << (r + 1)) + span + (g & (span - 1));
            bool bnew = (g & (span - 1)) == 0;
            const float* A = (r == 0)
                ? g_bufB + (size_t)((b * NSEGS + e_src) * SEGC + SEGC - 1) * STRIDE
                : g_T + (size_t)(b * NSEGS + e_src) * STRIDE;
            const float* Bp = bnew
                ? g_bufB + (size_t)((b * NSEGS + e_dst) * SEGC + SEGC - 1) * STRIDE
                : g_T + (size_t)(b * NSEGS + e_dst) * STRIDE;
            float* Od = g_T + (size_t)(b * NSEGS + e_dst) * STRIDE;
            ta_merge(A, Bp, Od, sm, tid);
        }
        gsync(2 + r);
    }

    // ======================= Phase 3: apply + log ===========================
    for (int it = 0; it < 4; it++) {
        __syncthreads();
        apply_one(blk + 256 * it, sm, tid);
    }
    gsync(7);

    // ======================= Phase 4: pool + GEMV partials ==================
    {
        int b = blk >> 5, sl = blk & 31;
        int i0 = sl * SLW;
        int len = SIZE - i0; if (len > SLW) len = SLW;
        float* pv = sm;
        __syncthreads();
        for (int t = tid; t < len; t += 256) {
            const float* p = g_bufA + (size_t)b * NCH * STRIDE + i0 + t;
            float acc = 0.0f;
            #pragma unroll 8
            for (int n = 0; n < NCH; n++) acc += __ldcg(p + (size_t)n * STRIDE);
            pv[t] = acc * (1.0f / NCH);
        }
        __syncthreads();
        float acc = 0.0f;
        for (int ii = 0; ii < len; ii++)
            acc = fmaf(pv[ii], __ldg(&W1[(size_t)(i0 + ii) * HDIM + tid]), acc);
        g_hp[(sl * BB + b) * HDIM + tid] = acc;
    }
    gsync(8);

    // ======================= Final: MLP head (block 0) ======================
    if (blk == 0) {
        float* red = sm;
        __syncthreads();
        for (int bb = 0; bb < BB; bb++) {
            float h = 0.0f;
            #pragma unroll
            for (int sl2 = 0; sl2 < NSL; sl2++)
                h += __ldcg(&g_hp[(sl2 * BB + bb) * HDIM + tid]);
            float v = fmaxf(h + b1[tid], 0.0f) * W2[tid];
            red[tid] = v; __syncthreads();
            for (int s2 = 128; s2 > 0; s2 >>= 1) {
                if (tid < s2) red[tid] += red[tid + s2];
                __syncthreads();
            }
            if (tid == 0) out[bb] = red[0] + b2[0];
            __syncthreads();
        }
        if (tid == 0) g_bar = 0u;   // reset for next launch (deterministic)
    }
}

// ---------------------------------------------------------------------------
extern "C" void kernel_launch(void* const* d_in, const int* in_sizes, int n_in,
                              void* d_out, int out_size)
{
    const float* x  = (const float*)d_in[0];
    const float* W1 = (const float*)d_in[1];
    const float* b1 = (const float*)d_in[2];
    const float* W2 = (const float*)d_in[3];
    const float* b2 = (const float*)d_in[4];
    float* out = (float*)d_out;

    (void)in_sizes; (void)n_in; (void)out_size;

    k_fused<<<NBLK, 256>>>(x, W1, b1, W2, b2, out);
}